// round 6
// baseline (speedup 1.0000x reference)
#include <cuda_runtime.h>
#include <cstdint>

// Problem constants
#define B_   32
#define C_   256
#define H_   58
#define W_   58
#define OC_  256
#define KH_  3
#define KW_  3
#define HO_  56
#define WO_  56
#define HW_  (H_*W_)            // 3364
#define NWORDS 8                // 256 channels / 32 bits
#define CN_  2304               // C*KH*KW
#define NINPUT 861184.0f        // C*H*W (alpha normalizer)

// Scratch (device globals; no allocations allowed)
__device__ unsigned g_xpack[B_ * HW_ * NWORDS];        // [b][y][x][w]  3.44 MB
__device__ unsigned g_wpack[OC_ * KH_ * KW_ * NWORDS]; // [o][k][w]     73.7 KB
__device__ float    g_alpha[OC_];

// Forced single-LOP3 3-input ops
template <int LUT>
__device__ __forceinline__ unsigned lop3(unsigned a, unsigned b, unsigned c) {
    unsigned r;
    asm("lop3.b32 %0, %1, %2, %3, %4;" : "=r"(r) : "r"(a), "r"(b), "r"(c), "n"(LUT));
    return r;
}
#define XOR3(a,b,c)  lop3<0x96>(a,b,c)                 // a^b^c
#define MAJ3(a,b,c)  lop3<0xE8>(a,b,c)                 // majority
#define MAJU(x,y,u)  lop3<0xD4>(x,y,u)                 // (x&y)|((x^y)&~u)

// ---------------------------------------------------------------------------
// Pass 1: pack binary activations over the channel dimension. (HBM-roofline)
// ---------------------------------------------------------------------------
__global__ void pack_x_kernel(const float* __restrict__ x) {
    int bw = blockIdx.x;
    int b  = bw >> 3;
    int w  = bw & 7;
    int pos = blockIdx.y * blockDim.x + threadIdx.x;
    if (pos >= HW_) return;

    const float* xp = x + ((size_t)(b * C_ + w * 32) * HW_) + pos;
    unsigned bits = 0;
#pragma unroll
    for (int c = 0; c < 32; c++) {
        float v = __ldg(xp + (size_t)c * HW_);
        bits |= (v > 0.5f ? 1u : 0u) << c;
    }
    g_xpack[((size_t)b * HW_ + pos) * NWORDS + w] = bits;
}

// ---------------------------------------------------------------------------
// Pass 2: pack binarized weights (ballot) + alpha per filter.
// ---------------------------------------------------------------------------
__global__ void pack_w_kernel(const float* __restrict__ wgt) {
    int o = blockIdx.x;
    int c = threadIdx.x;
    int lane = c & 31;
    int wrp  = c >> 5;

    const float* wp = wgt + (size_t)(o * C_ + c) * (KH_ * KW_);
    float asum = 0.f;
#pragma unroll
    for (int k = 0; k < KH_ * KW_; k++) {
        float v = wp[k];
        asum += fabsf(v);
        unsigned word = __ballot_sync(0xffffffffu, v >= 0.f);
        if (lane == 0) g_wpack[(o * 9 + k) * NWORDS + wrp] = word;
    }

    __shared__ float red[256];
    red[c] = asum;
    __syncthreads();
#pragma unroll
    for (int s = 128; s > 0; s >>= 1) {
        if (c < s) red[c] += red[c + s];
        __syncthreads();
    }
    if (c == 0) g_alpha[o] = red[0] / NINPUT;
}

// ---------------------------------------------------------------------------
// Pass 3: XNOR conv with TWO-LEVEL carry-save compression.
// Level 1 (kw taps): popc(x)+popc(y)+popc(z) = popc(u) + 2 popc(v)
//   u = s3 ^ wx3 (s3 = 3-col pixel XOR, shared in smem; wx3 per-thread)
//   v = (xw&yw)|((xw^yw)&~u)   [single LOP3; kw=2 pixel never touched]
// Level 2 (kh rows): su = u0^u1^u2, cu = maj(u0,u1,u2); same for v.
// Per word: 4 POPC with weights (1,2,2,4). Per output: 128 LOP3 + 32 POPC.
// grid = B_*HO_, block = 256 (thread = output channel), 4 outputs/step.
// ---------------------------------------------------------------------------
__global__ void __launch_bounds__(256, 2)
xnor_conv_kernel(float* __restrict__ out) {
    int by = blockIdx.x;
    int b  = by / HO_;
    int y  = by % HO_;
    int o  = threadIdx.x;

    __shared__ __align__(16) unsigned sx[3 * W_  * NWORDS];  // 5568 B
    __shared__ __align__(16) unsigned s3[3 * WO_ * NWORDS];  // 5376 B

    // load 3 packed rows
    const int ROW4 = W_ * NWORDS / 4; // 116 uint4 per row
    for (int i = threadIdx.x; i < 3 * ROW4; i += 256) {
        int kh = i / ROW4;
        int r  = i - kh * ROW4;
        const uint4* src = (const uint4*)(g_xpack + ((size_t)(b * H_ + y + kh) * W_) * NWORDS);
        ((uint4*)sx)[kh * ROW4 + r] = src[r];
    }

    // per-thread weights: w0, w1 (kw taps 0,1) and wx3 = w0^w1^w2, laid out [kh*8+w]
    unsigned w0[24], w1[24], wx3[24];
    {
        const uint4* wp4 = (const uint4*)(g_wpack + o * 72);
#pragma unroll
        for (int kh = 0; kh < 3; kh++) {
            uint4 a0 = wp4[(kh * 3 + 0) * 2], a1 = wp4[(kh * 3 + 0) * 2 + 1];
            uint4 b0 = wp4[(kh * 3 + 1) * 2], b1 = wp4[(kh * 3 + 1) * 2 + 1];
            uint4 c0 = wp4[(kh * 3 + 2) * 2], c1 = wp4[(kh * 3 + 2) * 2 + 1];
            ((uint4*)w0)[kh * 2] = a0; ((uint4*)w0)[kh * 2 + 1] = a1;
            ((uint4*)w1)[kh * 2] = b0; ((uint4*)w1)[kh * 2 + 1] = b1;
            wx3[kh * 8 + 0] = a0.x ^ b0.x ^ c0.x;
            wx3[kh * 8 + 1] = a0.y ^ b0.y ^ c0.y;
            wx3[kh * 8 + 2] = a0.z ^ b0.z ^ c0.z;
            wx3[kh * 8 + 3] = a0.w ^ b0.w ^ c0.w;
            wx3[kh * 8 + 4] = a1.x ^ b1.x ^ c1.x;
            wx3[kh * 8 + 5] = a1.y ^ b1.y ^ c1.y;
            wx3[kh * 8 + 6] = a1.z ^ b1.z ^ c1.z;
            wx3[kh * 8 + 7] = a1.w ^ b1.w ^ c1.w;
        }
    }
    float a = g_alpha[o];
    __syncthreads();

    // precompute s3[kh][c][w] = sx[kh][c] ^ sx[kh][c+1] ^ sx[kh][c+2]
    for (int i = threadIdx.x; i < 3 * WO_ * NWORDS; i += 256) {
        int kh = i / (WO_ * NWORDS);
        int r  = i - kh * (WO_ * NWORDS);
        int base = kh * (W_ * NWORDS) + r;
        s3[i] = XOR3(sx[base], sx[base + NWORDS], sx[base + 2 * NWORDS]);
    }
    __syncthreads();

    float* outp = out + ((size_t)(b * OC_ + o) * HO_ + y) * WO_;

#pragma unroll 1
    for (int x0 = 0; x0 < WO_; x0 += 4) {
        int P[4] = {0, 0, 0, 0};
#pragma unroll
        for (int w = 0; w < 8; w++) {
            unsigned u[3][4], v[3][4];
#pragma unroll
            for (int kh = 0; kh < 3; kh++) {
                const unsigned* rp = &sx[(kh * W_ + x0) * NWORDS + w];
                unsigned p0 = rp[0],  p1 = rp[8],  p2 = rp[16],
                         p3 = rp[24], p4 = rp[32];
                const unsigned* rs = &s3[(kh * WO_ + x0) * NWORDS + w];
                int wi = kh * 8 + w;
                unsigned W0 = w0[wi], W1 = w1[wi], WX = wx3[wi];
                u[kh][0] = rs[0]  ^ WX;
                u[kh][1] = rs[8]  ^ WX;
                u[kh][2] = rs[16] ^ WX;
                u[kh][3] = rs[24] ^ WX;
                v[kh][0] = MAJU(p0 ^ W0, p1 ^ W1, u[kh][0]);
                v[kh][1] = MAJU(p1 ^ W0, p2 ^ W1, u[kh][1]);
                v[kh][2] = MAJU(p2 ^ W0, p3 ^ W1, u[kh][2]);
                v[kh][3] = MAJU(p3 ^ W0, p4 ^ W1, u[kh][3]);
            }
#pragma unroll
            for (int xi = 0; xi < 4; xi++) {
                unsigned su = XOR3(u[0][xi], u[1][xi], u[2][xi]);
                unsigned cu = MAJ3(u[0][xi], u[1][xi], u[2][xi]);
                unsigned sv = XOR3(v[0][xi], v[1][xi], v[2][xi]);
                unsigned cv = MAJ3(v[0][xi], v[1][xi], v[2][xi]);
                P[xi] += __popc(su) + ((__popc(cu) + __popc(sv)) << 1)
                       + (__popc(cv) << 2);
            }
        }
        float4 r;
        r.x = a * (float)(CN_ - 2 * P[0]);
        r.y = a * (float)(CN_ - 2 * P[1]);
        r.z = a * (float)(CN_ - 2 * P[2]);
        r.w = a * (float)(CN_ - 2 * P[3]);
        *(float4*)(outp + x0) = r;
    }
}

// ---------------------------------------------------------------------------
extern "C" void kernel_launch(void* const* d_in, const int* in_sizes, int n_in,
                              void* d_out, int out_size) {
    const float* x   = (const float*)d_in[0];
    const float* wgt = (const float*)d_in[1];
    float* out = (float*)d_out;

    dim3 g1(B_ * NWORDS, (HW_ + 255) / 256);
    pack_x_kernel<<<g1, 256>>>(x);
    pack_w_kernel<<<OC_, 256>>>(wgt);
    xnor_conv_kernel<<<B_ * HO_, 256>>>(out);
}

// round 7
// speedup vs baseline: 1.5023x; 1.5023x over previous
#include <cuda_runtime.h>
#include <cstdint>

// Problem constants
#define B_   32
#define C_   256
#define H_   58
#define W_   58
#define OC_  256
#define KH_  3
#define KW_  3
#define HO_  56
#define WO_  56
#define HW_  (H_*W_)            // 3364
#define NWORDS 8                // 256 channels / 32 bits
#define CN_  2304               // C*KH*KW
#define NINPUT 861184.0f        // C*H*W (alpha normalizer)

// Scratch (device globals; no allocations allowed)
__device__ unsigned g_xpack[B_ * HW_ * NWORDS];        // [b][y][x][w]  3.44 MB
__device__ unsigned g_wpack[OC_ * KH_ * KW_ * NWORDS]; // [o][k][w]     73.7 KB
__device__ float    g_alpha[OC_];

// Forced single-LOP3 3-input ops
template <int LUT>
__device__ __forceinline__ unsigned lop3(unsigned a, unsigned b, unsigned c) {
    unsigned r;
    asm("lop3.b32 %0, %1, %2, %3, %4;" : "=r"(r) : "r"(a), "r"(b), "r"(c), "n"(LUT));
    return r;
}
#define XOR3(a,b,c)  lop3<0x96>(a,b,c)                 // a^b^c
#define MAJ3(a,b,c)  lop3<0xE8>(a,b,c)                 // majority
#define MAJU(x,y,u)  lop3<0xD4>(x,y,u)                 // (x&y)|((x^y)&~u)

// ---------------------------------------------------------------------------
// Pass 1: pack binary activations over the channel dimension. (HBM-roofline)
// ---------------------------------------------------------------------------
__global__ void pack_x_kernel(const float* __restrict__ x) {
    int bw = blockIdx.x;
    int b  = bw >> 3;
    int w  = bw & 7;
    int pos = blockIdx.y * blockDim.x + threadIdx.x;
    if (pos >= HW_) return;

    const float* xp = x + ((size_t)(b * C_ + w * 32) * HW_) + pos;
    unsigned bits = 0;
#pragma unroll
    for (int c = 0; c < 32; c++) {
        float v = __ldg(xp + (size_t)c * HW_);
        bits |= (v > 0.5f ? 1u : 0u) << c;
    }
    g_xpack[((size_t)b * HW_ + pos) * NWORDS + w] = bits;
}

// ---------------------------------------------------------------------------
// Pass 2: pack binarized weights (ballot) + alpha per filter.
// ---------------------------------------------------------------------------
__global__ void pack_w_kernel(const float* __restrict__ wgt) {
    int o = blockIdx.x;
    int c = threadIdx.x;
    int lane = c & 31;
    int wrp  = c >> 5;

    const float* wp = wgt + (size_t)(o * C_ + c) * (KH_ * KW_);
    float asum = 0.f;
#pragma unroll
    for (int k = 0; k < KH_ * KW_; k++) {
        float v = wp[k];
        asum += fabsf(v);
        unsigned word = __ballot_sync(0xffffffffu, v >= 0.f);
        if (lane == 0) g_wpack[(o * 9 + k) * NWORDS + wrp] = word;
    }

    __shared__ float red[256];
    red[c] = asum;
    __syncthreads();
#pragma unroll
    for (int s = 128; s > 0; s >>= 1) {
        if (c < s) red[c] += red[c + s];
        __syncthreads();
    }
    if (c == 0) g_alpha[o] = red[0] / NINPUT;
}

// ---------------------------------------------------------------------------
// Pass 3: XNOR conv, two-level CSA, vectorized smem reads.
// Level 1 (kw): popc(x)+popc(y)+popc(z) = popc(u) + 2 popc(v)
//   u = s3 ^ wx3 (s3 = 3-col pixel XOR in smem), v = MAJU(xw,yw,u).
// Level 2 (kh): u0..u2 -> su=XOR3, cu=MAJ3 (same for v); per word only
//   4 POPC with weights (1,2,2,4). POPC is the quarter-rate pipe: 32/output.
// Loads stay LDS.128 broadcast. 2 outputs/step; u/v held across kh in regs.
// grid = B_*HO_, block = 256 (thread = output channel).
// ---------------------------------------------------------------------------
__global__ void __launch_bounds__(256, 1)
xnor_conv_kernel(float* __restrict__ out) {
    int by = blockIdx.x;
    int b  = by / HO_;
    int y  = by % HO_;
    int o  = threadIdx.x;

    __shared__ __align__(16) unsigned sx[3 * W_  * NWORDS];  // 5568 B
    __shared__ __align__(16) unsigned s3[3 * WO_ * NWORDS];  // 5376 B

    // load 3 packed rows
    const int ROW4 = W_ * NWORDS / 4; // 116 uint4 per row
    for (int i = threadIdx.x; i < 3 * ROW4; i += 256) {
        int kh = i / ROW4;
        int r  = i - kh * ROW4;
        const uint4* src = (const uint4*)(g_xpack + ((size_t)(b * H_ + y + kh) * W_) * NWORDS);
        ((uint4*)sx)[kh * ROW4 + r] = src[r];
    }

    // per-thread weights: w0, w1 (kw taps 0,1) and wx3 = w0^w1^w2, [kh*8+w]
    unsigned w0[24], w1[24], wx3[24];
    {
        const uint4* wp4 = (const uint4*)(g_wpack + o * 72);
#pragma unroll
        for (int kh = 0; kh < 3; kh++) {
            uint4 a0 = wp4[(kh * 3 + 0) * 2], a1 = wp4[(kh * 3 + 0) * 2 + 1];
            uint4 b0 = wp4[(kh * 3 + 1) * 2], b1 = wp4[(kh * 3 + 1) * 2 + 1];
            uint4 c0 = wp4[(kh * 3 + 2) * 2], c1 = wp4[(kh * 3 + 2) * 2 + 1];
            ((uint4*)w0)[kh * 2] = a0; ((uint4*)w0)[kh * 2 + 1] = a1;
            ((uint4*)w1)[kh * 2] = b0; ((uint4*)w1)[kh * 2 + 1] = b1;
            wx3[kh * 8 + 0] = a0.x ^ b0.x ^ c0.x;
            wx3[kh * 8 + 1] = a0.y ^ b0.y ^ c0.y;
            wx3[kh * 8 + 2] = a0.z ^ b0.z ^ c0.z;
            wx3[kh * 8 + 3] = a0.w ^ b0.w ^ c0.w;
            wx3[kh * 8 + 4] = a1.x ^ b1.x ^ c1.x;
            wx3[kh * 8 + 5] = a1.y ^ b1.y ^ c1.y;
            wx3[kh * 8 + 6] = a1.z ^ b1.z ^ c1.z;
            wx3[kh * 8 + 7] = a1.w ^ b1.w ^ c1.w;
        }
    }
    float a = g_alpha[o];
    __syncthreads();

    // s3[kh][c][w] = sx[kh][c] ^ sx[kh][c+1] ^ sx[kh][c+2]
    for (int i = threadIdx.x; i < 3 * WO_ * NWORDS; i += 256) {
        int kh = i / (WO_ * NWORDS);
        int r  = i - kh * (WO_ * NWORDS);
        int base = kh * (W_ * NWORDS) + r;
        s3[i] = XOR3(sx[base], sx[base + NWORDS], sx[base + 2 * NWORDS]);
    }
    __syncthreads();

    float* outp = out + ((size_t)(b * OC_ + o) * HO_ + y) * WO_;

#pragma unroll 1
    for (int x0 = 0; x0 < WO_; x0 += 2) {
        int P0 = 0, P1 = 0;
#pragma unroll
        for (int half = 0; half < 2; half++) {
            unsigned u[3][2][4], v[3][2][4];     // [kh][xi][j]
#pragma unroll
            for (int kh = 0; kh < 3; kh++) {
                const unsigned* rp = &sx[(kh * W_ + x0) * NWORDS + half * 4];
                uint4 q0 = *(const uint4*)(rp);
                uint4 q1 = *(const uint4*)(rp + NWORDS);
                uint4 q2 = *(const uint4*)(rp + 2 * NWORDS);
                const unsigned* rs = &s3[(kh * WO_ + x0) * NWORDS + half * 4];
                uint4 t0 = *(const uint4*)(rs);
                uint4 t1 = *(const uint4*)(rs + NWORDS);
                unsigned p0[4] = {q0.x, q0.y, q0.z, q0.w};
                unsigned p1[4] = {q1.x, q1.y, q1.z, q1.w};
                unsigned p2[4] = {q2.x, q2.y, q2.z, q2.w};
                unsigned s0[4] = {t0.x, t0.y, t0.z, t0.w};
                unsigned s1[4] = {t1.x, t1.y, t1.z, t1.w};
#pragma unroll
                for (int j = 0; j < 4; j++) {
                    int wi = kh * 8 + half * 4 + j;
                    unsigned W0 = w0[wi], W1 = w1[wi], WX = wx3[wi];
                    unsigned u0 = s0[j] ^ WX;
                    unsigned u1 = s1[j] ^ WX;
                    u[kh][0][j] = u0;
                    u[kh][1][j] = u1;
                    v[kh][0][j] = MAJU(p0[j] ^ W0, p1[j] ^ W1, u0);
                    v[kh][1][j] = MAJU(p1[j] ^ W0, p2[j] ^ W1, u1);
                }
            }
#pragma unroll
            for (int xi = 0; xi < 2; xi++) {
#pragma unroll
                for (int j = 0; j < 4; j++) {
                    unsigned su = XOR3(u[0][xi][j], u[1][xi][j], u[2][xi][j]);
                    unsigned cu = MAJ3(u[0][xi][j], u[1][xi][j], u[2][xi][j]);
                    unsigned sv = XOR3(v[0][xi][j], v[1][xi][j], v[2][xi][j]);
                    unsigned cv = MAJ3(v[0][xi][j], v[1][xi][j], v[2][xi][j]);
                    int t = __popc(su) + ((__popc(cu) + __popc(sv)) << 1)
                          + (__popc(cv) << 2);
                    if (xi == 0) P0 += t; else P1 += t;
                }
            }
        }
        float2 r;
        r.x = a * (float)(CN_ - 2 * P0);
        r.y = a * (float)(CN_ - 2 * P1);
        *(float2*)(outp + x0) = r;
    }
}

// ---------------------------------------------------------------------------
extern "C" void kernel_launch(void* const* d_in, const int* in_sizes, int n_in,
                              void* d_out, int out_size) {
    const float* x   = (const float*)d_in[0];
    const float* wgt = (const float*)d_in[1];
    float* out = (float*)d_out;

    dim3 g1(B_ * NWORDS, (HW_ + 255) / 256);
    pack_x_kernel<<<g1, 256>>>(x);
    pack_w_kernel<<<OC_, 256>>>(wgt);
    xnor_conv_kernel<<<B_ * HO_, 256>>>(out);
}